// round 11
// baseline (speedup 1.0000x reference)
#include <cuda_runtime.h>
#include <cuda_fp16.h>

// ---------------------------------------------------------------------------
// GCN_11682311045288: 2-layer GCN via per-launch CSR build + gather aggregation.
// fp16 edge-message table; fp32 self-loop+bias path; f32x2 packed GEMM.
// Inputs: x [N,128] f32, edge_index [2,E] int32, W1[128,64], b1[64], W2[64,64], b2[64]
// Output: z [N,64] f32
// ---------------------------------------------------------------------------

#define MAXN 131072
#define MAXE 2097152
#define F 64
#define F4 (F / 4)    // float4 groups per fp32 row: 16
#define FH16 16       // uint2 (4 halves) groups per fp16 row
#define XST 72        // xst row stride in floats (16B-aligned for all k)

typedef unsigned long long u64;

// Scratch (module-load allocated; allowed).
__device__ uint2  g_xwh[(size_t)MAXN * FH16]; // fp16 XW table, 128B per row
__device__ float4 g_h [(size_t)MAXN * F4];    // layer-1 result / layer-2 input
__device__ float  g_dinv[MAXN];
__device__ int    g_deg [MAXN];
__device__ int    g_rowptr[MAXN];             // after k_fill: row end
__device__ int    g_part[512];
__device__ int2   g_csr[MAXE];

__device__ __forceinline__ float2 h2f(unsigned u) {
    __half2 h = *reinterpret_cast<__half2*>(&u);
    return __half22float2(h);
}
__device__ __forceinline__ u64 pack2(float lo, float hi) {
    u64 r;
    asm("mov.b64 %0, {%1, %2};" : "=l"(r) : "r"(__float_as_uint(lo)), "r"(__float_as_uint(hi)));
    return r;
}
__device__ __forceinline__ void unpack2(u64 v, float& lo, float& hi) {
    unsigned a, b;
    asm("mov.b64 {%0, %1}, %2;" : "=r"(a), "=r"(b) : "l"(v));
    lo = __uint_as_float(a); hi = __uint_as_float(b);
}
__device__ __forceinline__ void fma2(u64& acc, u64 a, u64 b) {
    asm("fma.rn.f32x2 %0, %1, %2, %0;" : "+l"(acc) : "l"(a), "l"(b));
}

// ---------------------------------------------------------------------------
__global__ void k_deg_count(const int* __restrict__ dst, int E) {
    int i = blockIdx.x * blockDim.x + threadIdx.x;
    int stride = gridDim.x * blockDim.x;
    int E4 = E >> 2;
    const int4* dst4 = (const int4*)dst;
    for (int j = i; j < E4; j += stride) {
        int4 d = dst4[j];
        atomicAdd(&g_deg[d.x], 1);
        atomicAdd(&g_deg[d.y], 1);
        atomicAdd(&g_deg[d.z], 1);
        atomicAdd(&g_deg[d.w], 1);
    }
    for (int j = (E4 << 2) + i; j < E; j += stride)
        atomicAdd(&g_deg[dst[j]], 1);
}

// --- 3-phase exclusive scan of g_deg -> g_rowptr ---------------------------
__global__ void k_scan_part(int n) {
    __shared__ int s[256];
    int t = threadIdx.x;
    int i = blockIdx.x * 256 + t;
    int v = (i < n) ? g_deg[i] : 0;
    s[t] = v;
    __syncthreads();
    #pragma unroll
    for (int off = 1; off < 256; off <<= 1) {
        int u = (t >= off) ? s[t - off] : 0;
        __syncthreads();
        s[t] += u;
        __syncthreads();
    }
    if (i < n) g_rowptr[i] = s[t] - v;
    if (t == 255) g_part[blockIdx.x] = s[255];
}

__global__ void k_scan_mid(int nb) {
    __shared__ int s[512];
    int t = threadIdx.x;
    int v = (t < nb) ? g_part[t] : 0;
    s[t] = v;
    __syncthreads();
    #pragma unroll
    for (int off = 1; off < 512; off <<= 1) {
        int u = (t >= off) ? s[t - off] : 0;
        __syncthreads();
        s[t] += u;
        __syncthreads();
    }
    if (t < nb) g_part[t] = s[t] - v;
}

__global__ void k_scan_apply(int n) {
    int i = blockIdx.x * 256 + threadIdx.x;
    if (i < n) {
        g_rowptr[i] += g_part[blockIdx.x];
        g_dinv[i] = rsqrtf((float)(g_deg[i] + 1));
    }
}

// Bumps g_rowptr[d]; after this kernel g_rowptr[i] = row end.
__global__ void k_fill(const int* __restrict__ src,
                       const int* __restrict__ dst, int E) {
    int i = blockIdx.x * blockDim.x + threadIdx.x;
    int stride = gridDim.x * blockDim.x;
    int E4 = E >> 2;
    const int4* src4 = (const int4*)src;
    const int4* dst4 = (const int4*)dst;
    for (int j = i; j < E4; j += stride) {
        int4 s = src4[j];
        int4 d = dst4[j];
        int p0 = atomicAdd(&g_rowptr[d.x], 1);
        g_csr[p0] = make_int2(s.x, __float_as_int(g_dinv[s.x] * g_dinv[d.x]));
        int p1 = atomicAdd(&g_rowptr[d.y], 1);
        g_csr[p1] = make_int2(s.y, __float_as_int(g_dinv[s.y] * g_dinv[d.y]));
        int p2 = atomicAdd(&g_rowptr[d.z], 1);
        g_csr[p2] = make_int2(s.z, __float_as_int(g_dinv[s.z] * g_dinv[d.z]));
        int p3 = atomicAdd(&g_rowptr[d.w], 1);
        g_csr[p3] = make_int2(s.w, __float_as_int(g_dinv[s.w] * g_dinv[d.w]));
    }
    for (int j = (E4 << 2) + i; j < E; j += stride) {
        int s = src[j], d = dst[j];
        int p = atomicAdd(&g_rowptr[d], 1);
        g_csr[p] = make_int2(s, __float_as_int(g_dinv[s] * g_dinv[d]));
    }
}

// ---------------------------------------------------------------------------
// Register-tiled GEMM (f32x2 packed): C[64x64]/block, 256 threads,
// 16 outputs/thread as 8 packed accumulators. xst stride 72 floats keeps
// every 16B vector LDS aligned. Emits fp16 table row + fp32 init row.
template<int K, bool RELU, bool READ_GH, bool STORE_GH>
__global__ void k_gemm(const float* __restrict__ Xp,
                       const float* __restrict__ W,
                       const float* __restrict__ bias,
                       float* __restrict__ outp,
                       int n)
{
    __shared__ float Ws[K * 64];
    __shared__ float xst[K * XST];

    const float* __restrict__ X = READ_GH ? (const float*)g_h : Xp;
    float* __restrict__ oinit = STORE_GH ? (float*)g_h : outp;
    __half* __restrict__ xwh = (__half*)g_xwh;

    int tid = threadIdx.x;
    int f = tid & 63;
    int g = tid >> 6;
    int row0 = blockIdx.x * 64;

    {
        const float4* W4 = (const float4*)W;
        #pragma unroll
        for (int i = tid; i < K * 16; i += 256)
            ((float4*)Ws)[i] = W4[i];
    }
    {
        const int KQ = K / 4;
        #pragma unroll
        for (int i = tid; i < 64 * KQ; i += 256) {
            int r = i / KQ;
            int k4 = (i - r * KQ) * 4;
            int rr = row0 + r;
            float4 v = make_float4(0.f, 0.f, 0.f, 0.f);
            if (rr < n)
                v = ((const float4*)X)[((size_t)rr * K + k4) >> 2];
            if (RELU) {
                v.x = fmaxf(v.x, 0.f); v.y = fmaxf(v.y, 0.f);
                v.z = fmaxf(v.z, 0.f); v.w = fmaxf(v.w, 0.f);
            }
            xst[(k4 + 0) * XST + r] = v.x;
            xst[(k4 + 1) * XST + r] = v.y;
            xst[(k4 + 2) * XST + r] = v.z;
            xst[(k4 + 3) * XST + r] = v.w;
        }
    }
    __syncthreads();

    u64 accp[8];
    #pragma unroll
    for (int i = 0; i < 8; ++i) accp[i] = 0ull;
    const int rbase = g * 16;

    #pragma unroll 4
    for (int k = 0; k < K; ++k) {
        float wv = Ws[k * 64 + f];
        u64 wp = pack2(wv, wv);
        // 16B-aligned: XST*k + 16*g is a multiple of 4 floats for all k,g
        const ulonglong2* xr = (const ulonglong2*)&xst[k * XST + rbase];
        ulonglong2 q0 = xr[0], q1 = xr[1], q2 = xr[2], q3 = xr[3];
        fma2(accp[0], q0.x, wp);
        fma2(accp[1], q0.y, wp);
        fma2(accp[2], q1.x, wp);
        fma2(accp[3], q1.y, wp);
        fma2(accp[4], q2.x, wp);
        fma2(accp[5], q2.y, wp);
        fma2(accp[6], q3.x, wp);
        fma2(accp[7], q3.y, wp);
    }

    float bf = bias[f];
    #pragma unroll
    for (int i = 0; i < 8; ++i) {
        float lo, hi;
        unpack2(accp[i], lo, hi);
        int r0 = row0 + rbase + 2 * i;
        if (r0 < n) {
            xwh[(size_t)r0 * 64 + f] = __float2half_rn(lo);
            float di = g_dinv[r0];
            oinit[(size_t)r0 * 64 + f] = fmaf(di * di, lo, bf);
        }
        if (r0 + 1 < n) {
            xwh[(size_t)(r0 + 1) * 64 + f] = __float2half_rn(hi);
            float di = g_dinv[r0 + 1];
            oinit[(size_t)(r0 + 1) * 64 + f] = fmaf(di * di, hi, bf);
        }
    }
}

// ---------------------------------------------------------------------------
// Gather aggregation: half-warp (16 lanes) per node, lane owns 4 features.
// Gathers fp16 rows (uint2 per lane, L2-only), accumulates fp32,
// adds the GEMM-written fp32 init row, stores fp32.
template<bool TO_GH>
__global__ void k_aggr(float4* __restrict__ outp, int n)
{
    float4* __restrict__ o = TO_GH ? g_h : outp;
    const uint2* __restrict__ xwh = g_xwh;

    int gtid = blockIdx.x * blockDim.x + threadIdx.x;
    int node = gtid >> 4;
    int lane = threadIdx.x & 15;
    if (node >= n) return;

    int end = g_rowptr[node];
    int deg = g_deg[node];
    int beg = end - deg;

    float4 acc = make_float4(0.f, 0.f, 0.f, 0.f);
    int e = beg;
    for (; e + 8 <= end; e += 8) {
        int2 sw0 = g_csr[e];
        int2 sw1 = g_csr[e + 1];
        int2 sw2 = g_csr[e + 2];
        int2 sw3 = g_csr[e + 3];
        int2 sw4 = g_csr[e + 4];
        int2 sw5 = g_csr[e + 5];
        int2 sw6 = g_csr[e + 6];
        int2 sw7 = g_csr[e + 7];
        uint2 q0 = __ldcg(xwh + (size_t)sw0.x * FH16 + lane);
        uint2 q1 = __ldcg(xwh + (size_t)sw1.x * FH16 + lane);
        uint2 q2 = __ldcg(xwh + (size_t)sw2.x * FH16 + lane);
        uint2 q3 = __ldcg(xwh + (size_t)sw3.x * FH16 + lane);
        uint2 q4 = __ldcg(xwh + (size_t)sw4.x * FH16 + lane);
        uint2 q5 = __ldcg(xwh + (size_t)sw5.x * FH16 + lane);
        uint2 q6 = __ldcg(xwh + (size_t)sw6.x * FH16 + lane);
        uint2 q7 = __ldcg(xwh + (size_t)sw7.x * FH16 + lane);
        #define ACC_EDGE(q, sw) do {                                         \
            float w_ = __int_as_float((sw).y);                               \
            float2 a_ = h2f((q).x);                                          \
            float2 b_ = h2f((q).y);                                          \
            acc.x = fmaf(w_, a_.x, acc.x); acc.y = fmaf(w_, a_.y, acc.y);    \
            acc.z = fmaf(w_, b_.x, acc.z); acc.w = fmaf(w_, b_.y, acc.w);    \
        } while (0)
        ACC_EDGE(q0, sw0); ACC_EDGE(q1, sw1); ACC_EDGE(q2, sw2); ACC_EDGE(q3, sw3);
        ACC_EDGE(q4, sw4); ACC_EDGE(q5, sw5); ACC_EDGE(q6, sw6); ACC_EDGE(q7, sw7);
    }
    for (; e < end; ++e) {
        int2 sw = g_csr[e];
        uint2 q = __ldcg(xwh + (size_t)sw.x * FH16 + lane);
        ACC_EDGE(q, sw);
    }
    #undef ACC_EDGE

    float4* p = o + (size_t)node * F4 + lane;
    float4 init = *p;
    init.x += acc.x; init.y += acc.y; init.z += acc.z; init.w += acc.w;
    *p = init;
}

// ---------------------------------------------------------------------------
extern "C" void kernel_launch(void* const* d_in, const int* in_sizes, int n_in,
                              void* d_out, int out_size)
{
    const float* x  = (const float*)d_in[0];
    const int*   ei = (const int*)d_in[1];
    const float* W1 = (const float*)d_in[2];
    const float* b1 = (const float*)d_in[3];
    const float* W2 = (const float*)d_in[4];
    const float* b2 = (const float*)d_in[5];
    float* out = (float*)d_out;

    const int IN = 128;
    int N = in_sizes[0] / IN;
    int E = in_sizes[1] / 2;
    const int* src = ei;
    const int* dst = ei + E;

    int nb256 = (N + 255) / 256;
    int gemm_blocks = (N + 63) / 64;
    int edge_blocks = 1184;
    int aggr_blocks = (N + 15) / 16;

    // --- graph preprocessing ---
    void* degptr = nullptr;
    cudaGetSymbolAddress(&degptr, g_deg);
    cudaMemsetAsync(degptr, 0, (size_t)N * sizeof(int));
    k_deg_count<<<edge_blocks, 256>>>(dst, E);
    k_scan_part<<<nb256, 256>>>(N);
    k_scan_mid<<<1, 512>>>(nb256);
    k_scan_apply<<<nb256, 256>>>(N);
    k_fill<<<edge_blocks, 256>>>(src, dst, E);

    // --- layer 1: init rows -> g_h, aggregate into g_h ---
    k_gemm<128, false, false, true><<<gemm_blocks, 256>>>(x, W1, b1, nullptr, N);
    k_aggr<true><<<aggr_blocks, 256>>>(nullptr, N);

    // --- layer 2: init rows -> out, aggregate into out ---
    k_gemm<64, true, true, false><<<gemm_blocks, 256>>>(nullptr, W2, b2, out, N);
    k_aggr<false><<<aggr_blocks, 256>>>((float4*)out, N);
}

// round 12
// speedup vs baseline: 1.1334x; 1.1334x over previous
#include <cuda_runtime.h>
#include <cuda_fp16.h>

// ---------------------------------------------------------------------------
// GCN_11682311045288: 2-layer GCN via per-launch CSR build + gather aggregation.
// fp16 edge-message table (128B rows); fp32 self-loop+bias path; scalar GEMM.
// Inputs: x [N,128] f32, edge_index [2,E] int32, W1[128,64], b1[64], W2[64,64], b2[64]
// Output: z [N,64] f32
// ---------------------------------------------------------------------------

#define MAXN 131072
#define MAXE 2097152
#define F 64
#define F4 (F / 4)    // float4 groups per fp32 row: 16
#define FU4 8         // uint4 (8 halves) groups per fp16 row: 64/8 = 8

// Scratch (module-load allocated; allowed).
__device__ uint4  g_xwh[(size_t)MAXN * FU4];  // fp16 XW table, 128B per row
__device__ float4 g_h [(size_t)MAXN * F4];    // layer-1 result / layer-2 input
__device__ float  g_dinv[MAXN];
__device__ int    g_deg [MAXN];
__device__ int    g_rowptr[MAXN];             // after k_fill: row end
__device__ int    g_part[512];
__device__ int2   g_csr[MAXE];

__device__ __forceinline__ float2 h2f(unsigned u) {
    __half2 h = *reinterpret_cast<__half2*>(&u);
    return __half22float2(h);
}

// ---------------------------------------------------------------------------
__global__ void k_deg_count(const int* __restrict__ dst, int E) {
    int i = blockIdx.x * blockDim.x + threadIdx.x;
    int stride = gridDim.x * blockDim.x;
    int E4 = E >> 2;
    const int4* dst4 = (const int4*)dst;
    for (int j = i; j < E4; j += stride) {
        int4 d = dst4[j];
        atomicAdd(&g_deg[d.x], 1);
        atomicAdd(&g_deg[d.y], 1);
        atomicAdd(&g_deg[d.z], 1);
        atomicAdd(&g_deg[d.w], 1);
    }
    for (int j = (E4 << 2) + i; j < E; j += stride)
        atomicAdd(&g_deg[dst[j]], 1);
}

// --- 3-phase exclusive scan of g_deg -> g_rowptr ---------------------------
__global__ void k_scan_part(int n) {
    __shared__ int s[256];
    int t = threadIdx.x;
    int i = blockIdx.x * 256 + t;
    int v = (i < n) ? g_deg[i] : 0;
    s[t] = v;
    __syncthreads();
    #pragma unroll
    for (int off = 1; off < 256; off <<= 1) {
        int u = (t >= off) ? s[t - off] : 0;
        __syncthreads();
        s[t] += u;
        __syncthreads();
    }
    if (i < n) g_rowptr[i] = s[t] - v;
    if (t == 255) g_part[blockIdx.x] = s[255];
}

__global__ void k_scan_mid(int nb) {
    __shared__ int s[512];
    int t = threadIdx.x;
    int v = (t < nb) ? g_part[t] : 0;
    s[t] = v;
    __syncthreads();
    #pragma unroll
    for (int off = 1; off < 512; off <<= 1) {
        int u = (t >= off) ? s[t - off] : 0;
        __syncthreads();
        s[t] += u;
        __syncthreads();
    }
    if (t < nb) g_part[t] = s[t] - v;
}

__global__ void k_scan_apply(int n) {
    int i = blockIdx.x * 256 + threadIdx.x;
    if (i < n) {
        g_rowptr[i] += g_part[blockIdx.x];
        g_dinv[i] = rsqrtf((float)(g_deg[i] + 1));
    }
}

// Bumps g_rowptr[d]; after this kernel g_rowptr[i] = row end.
__global__ void k_fill(const int* __restrict__ src,
                       const int* __restrict__ dst, int E) {
    int i = blockIdx.x * blockDim.x + threadIdx.x;
    int stride = gridDim.x * blockDim.x;
    int E4 = E >> 2;
    const int4* src4 = (const int4*)src;
    const int4* dst4 = (const int4*)dst;
    for (int j = i; j < E4; j += stride) {
        int4 s = src4[j];
        int4 d = dst4[j];
        int p0 = atomicAdd(&g_rowptr[d.x], 1);
        g_csr[p0] = make_int2(s.x, __float_as_int(g_dinv[s.x] * g_dinv[d.x]));
        int p1 = atomicAdd(&g_rowptr[d.y], 1);
        g_csr[p1] = make_int2(s.y, __float_as_int(g_dinv[s.y] * g_dinv[d.y]));
        int p2 = atomicAdd(&g_rowptr[d.z], 1);
        g_csr[p2] = make_int2(s.z, __float_as_int(g_dinv[s.z] * g_dinv[d.z]));
        int p3 = atomicAdd(&g_rowptr[d.w], 1);
        g_csr[p3] = make_int2(s.w, __float_as_int(g_dinv[s.w] * g_dinv[d.w]));
    }
    for (int j = (E4 << 2) + i; j < E; j += stride) {
        int s = src[j], d = dst[j];
        int p = atomicAdd(&g_rowptr[d], 1);
        g_csr[p] = make_int2(s, __float_as_int(g_dinv[s] * g_dinv[d]));
    }
}

// ---------------------------------------------------------------------------
// Register-tiled GEMM: C[64x64] per block, 256 threads, 16 outputs/thread.
// Emits: fp16 table row (for edge gathers) + fp32 init = dinv^2*acc + bias.
template<int K, bool RELU, bool READ_GH, bool STORE_GH>
__global__ void k_gemm(const float* __restrict__ Xp,
                       const float* __restrict__ W,
                       const float* __restrict__ bias,
                       float* __restrict__ outp,
                       int n)
{
    __shared__ float Ws[K * 64];
    __shared__ float xst[K * 68];

    const float* __restrict__ X = READ_GH ? (const float*)g_h : Xp;
    float* __restrict__ oinit = STORE_GH ? (float*)g_h : outp;
    __half* __restrict__ xwh = (__half*)g_xwh;

    int tid = threadIdx.x;
    int f = tid & 63;
    int g = tid >> 6;
    int row0 = blockIdx.x * 64;

    {
        const float4* W4 = (const float4*)W;
        #pragma unroll
        for (int i = tid; i < K * 16; i += 256)
            ((float4*)Ws)[i] = W4[i];
    }
    {
        const int KQ = K / 4;
        #pragma unroll
        for (int i = tid; i < 64 * KQ; i += 256) {
            int r = i / KQ;
            int k4 = (i - r * KQ) * 4;
            int rr = row0 + r;
            float4 v = make_float4(0.f, 0.f, 0.f, 0.f);
            if (rr < n)
                v = ((const float4*)X)[((size_t)rr * K + k4) >> 2];
            if (RELU) {
                v.x = fmaxf(v.x, 0.f); v.y = fmaxf(v.y, 0.f);
                v.z = fmaxf(v.z, 0.f); v.w = fmaxf(v.w, 0.f);
            }
            xst[(k4 + 0) * 68 + r] = v.x;
            xst[(k4 + 1) * 68 + r] = v.y;
            xst[(k4 + 2) * 68 + r] = v.z;
            xst[(k4 + 3) * 68 + r] = v.w;
        }
    }
    __syncthreads();

    float acc[16];
    #pragma unroll
    for (int i = 0; i < 16; ++i) acc[i] = 0.f;
    const int rbase = g * 16;

    #pragma unroll 4
    for (int k = 0; k < K; ++k) {
        float wv = Ws[k * 64 + f];
        const float4* xr = (const float4*)&xst[k * 68 + rbase];
        float4 a = xr[0], b = xr[1], c = xr[2], d = xr[3];
        acc[0]  = fmaf(a.x, wv, acc[0]);
        acc[1]  = fmaf(a.y, wv, acc[1]);
        acc[2]  = fmaf(a.z, wv, acc[2]);
        acc[3]  = fmaf(a.w, wv, acc[3]);
        acc[4]  = fmaf(b.x, wv, acc[4]);
        acc[5]  = fmaf(b.y, wv, acc[5]);
        acc[6]  = fmaf(b.z, wv, acc[6]);
        acc[7]  = fmaf(b.w, wv, acc[7]);
        acc[8]  = fmaf(c.x, wv, acc[8]);
        acc[9]  = fmaf(c.y, wv, acc[9]);
        acc[10] = fmaf(c.z, wv, acc[10]);
        acc[11] = fmaf(c.w, wv, acc[11]);
        acc[12] = fmaf(d.x, wv, acc[12]);
        acc[13] = fmaf(d.y, wv, acc[13]);
        acc[14] = fmaf(d.z, wv, acc[14]);
        acc[15] = fmaf(d.w, wv, acc[15]);
    }

    float bf = bias[f];
    #pragma unroll
    for (int i = 0; i < 16; ++i) {
        int r = row0 + rbase + i;
        if (r < n) {
            xwh[(size_t)r * 64 + f] = __float2half_rn(acc[i]);
            float di = g_dinv[r];
            oinit[(size_t)r * 64 + f] = fmaf(di * di, acc[i], bf);
        }
    }
}

// ---------------------------------------------------------------------------
// Gather aggregation: 8-lane group per node, lane owns 8 features (uint4 =
// 8 halves, one 16B L2-only load per edge per lane). Accumulates fp32, adds
// the GEMM-written fp32 init rows, stores fp32.
template<bool TO_GH>
__global__ void k_aggr(float4* __restrict__ outp, int n)
{
    float4* __restrict__ o = TO_GH ? g_h : outp;
    const uint4* __restrict__ xwh = g_xwh;

    int gtid = blockIdx.x * blockDim.x + threadIdx.x;
    int node = gtid >> 3;
    int lane = threadIdx.x & 7;
    if (node >= n) return;

    int end = g_rowptr[node];
    int deg = g_deg[node];
    int beg = end - deg;

    float acc[8];
    #pragma unroll
    for (int i = 0; i < 8; ++i) acc[i] = 0.f;

    #define ACC_EDGE(q, sw) do {                                             \
        float w_ = __int_as_float((sw).y);                                   \
        float2 p0_ = h2f((q).x);                                             \
        float2 p1_ = h2f((q).y);                                             \
        float2 p2_ = h2f((q).z);                                             \
        float2 p3_ = h2f((q).w);                                             \
        acc[0] = fmaf(w_, p0_.x, acc[0]); acc[1] = fmaf(w_, p0_.y, acc[1]);  \
        acc[2] = fmaf(w_, p1_.x, acc[2]); acc[3] = fmaf(w_, p1_.y, acc[3]);  \
        acc[4] = fmaf(w_, p2_.x, acc[4]); acc[5] = fmaf(w_, p2_.y, acc[5]);  \
        acc[6] = fmaf(w_, p3_.x, acc[6]); acc[7] = fmaf(w_, p3_.y, acc[7]);  \
    } while (0)

    int e = beg;
    for (; e + 4 <= end; e += 4) {
        int2 sw0 = g_csr[e];
        int2 sw1 = g_csr[e + 1];
        int2 sw2 = g_csr[e + 2];
        int2 sw3 = g_csr[e + 3];
        uint4 q0 = __ldcg(xwh + (size_t)sw0.x * FU4 + lane);
        uint4 q1 = __ldcg(xwh + (size_t)sw1.x * FU4 + lane);
        uint4 q2 = __ldcg(xwh + (size_t)sw2.x * FU4 + lane);
        uint4 q3 = __ldcg(xwh + (size_t)sw3.x * FU4 + lane);
        ACC_EDGE(q0, sw0);
        ACC_EDGE(q1, sw1);
        ACC_EDGE(q2, sw2);
        ACC_EDGE(q3, sw3);
    }
    for (; e < end; ++e) {
        int2 sw = g_csr[e];
        uint4 q = __ldcg(xwh + (size_t)sw.x * FU4 + lane);
        ACC_EDGE(q, sw);
    }
    #undef ACC_EDGE

    // lane owns float4 slots 2*lane and 2*lane+1 of the fp32 row
    float4* p = o + (size_t)node * F4 + 2 * lane;
    float4 i0 = p[0];
    float4 i1 = p[1];
    i0.x += acc[0]; i0.y += acc[1]; i0.z += acc[2]; i0.w += acc[3];
    i1.x += acc[4]; i1.y += acc[5]; i1.z += acc[6]; i1.w += acc[7];
    p[0] = i0;
    p[1] = i1;
}

// ---------------------------------------------------------------------------
extern "C" void kernel_launch(void* const* d_in, const int* in_sizes, int n_in,
                              void* d_out, int out_size)
{
    const float* x  = (const float*)d_in[0];
    const int*   ei = (const int*)d_in[1];
    const float* W1 = (const float*)d_in[2];
    const float* b1 = (const float*)d_in[3];
    const float* W2 = (const float*)d_in[4];
    const float* b2 = (const float*)d_in[5];
    float* out = (float*)d_out;

    const int IN = 128;
    int N = in_sizes[0] / IN;
    int E = in_sizes[1] / 2;
    const int* src = ei;
    const int* dst = ei + E;

    int nb256 = (N + 255) / 256;
    int gemm_blocks = (N + 63) / 64;
    int edge_blocks = 1184;
    int aggr_blocks = (N + 31) / 32;   // 32 nodes per 256-thread block

    // --- graph preprocessing ---
    void* degptr = nullptr;
    cudaGetSymbolAddress(&degptr, g_deg);
    cudaMemsetAsync(degptr, 0, (size_t)N * sizeof(int));
    k_deg_count<<<edge_blocks, 256>>>(dst, E);
    k_scan_part<<<nb256, 256>>>(N);
    k_scan_mid<<<1, 512>>>(nb256);
    k_scan_apply<<<nb256, 256>>>(N);
    k_fill<<<edge_blocks, 256>>>(src, dst, E);

    // --- layer 1: init rows -> g_h, aggregate into g_h ---
    k_gemm<128, false, false, true><<<gemm_blocks, 256>>>(x, W1, b1, nullptr, N);
    k_aggr<true><<<aggr_blocks, 256>>>(nullptr, N);

    // --- layer 2: init rows -> out, aggregate into out ---
    k_gemm<64, true, true, false><<<gemm_blocks, 256>>>(nullptr, W2, b2, out, N);
    k_aggr<false><<<aggr_blocks, 256>>>((float4*)out, N);
}

// round 13
// speedup vs baseline: 1.6086x; 1.4193x over previous
#include <cuda_runtime.h>
#include <cuda_fp16.h>

// ---------------------------------------------------------------------------
// GCN_11682311045288: 2-layer GCN via per-launch CSR build + gather aggregation.
// fp16 edge-message table; fp32 self-loop+bias path; tensor-core (HMMA) GEMM.
// Inputs: x [N,128] f32, edge_index [2,E] int32, W1[128,64], b1[64], W2[64,64], b2[64]
// Output: z [N,64] f32
// ---------------------------------------------------------------------------

#define MAXN 131072
#define MAXE 2097152
#define F 64
#define F4 (F / 4)    // float4 groups per fp32 row: 16
#define FU4 8         // uint4 (8 halves) groups per fp16 row: 64/8 = 8

// Scratch (module-load allocated; allowed).
__device__ uint4  g_xwh[(size_t)MAXN * FU4];  // fp16 XW table, 128B per row
__device__ float4 g_h [(size_t)MAXN * F4];    // layer-1 result / layer-2 input
__device__ float  g_dinv[MAXN];
__device__ int    g_deg [MAXN];
__device__ int    g_rowptr[MAXN];             // after k_fill: row end
__device__ int    g_part[512];
__device__ int2   g_csr[MAXE];

__device__ __forceinline__ float2 h2f(unsigned u) {
    __half2 h = *reinterpret_cast<__half2*>(&u);
    return __half22float2(h);
}
__device__ __forceinline__ unsigned s2u(const void* p) {
    return (unsigned)__cvta_generic_to_shared(p);
}
__device__ __forceinline__ void ldmx4(unsigned* r, unsigned addr) {
    asm volatile("ldmatrix.sync.aligned.m8n8.x4.shared.b16 {%0,%1,%2,%3}, [%4];"
                 : "=r"(r[0]), "=r"(r[1]), "=r"(r[2]), "=r"(r[3]) : "r"(addr));
}
__device__ __forceinline__ void ldmx4t(unsigned* r, unsigned addr) {
    asm volatile("ldmatrix.sync.aligned.m8n8.x4.trans.shared.b16 {%0,%1,%2,%3}, [%4];"
                 : "=r"(r[0]), "=r"(r[1]), "=r"(r[2]), "=r"(r[3]) : "r"(addr));
}
__device__ __forceinline__ void mma16816(float* d, const unsigned* a, const unsigned* b) {
    asm volatile(
        "mma.sync.aligned.m16n8k16.row.col.f32.f16.f16.f32 "
        "{%0,%1,%2,%3}, {%4,%5,%6,%7}, {%8,%9}, {%0,%1,%2,%3};"
        : "+f"(d[0]), "+f"(d[1]), "+f"(d[2]), "+f"(d[3])
        : "r"(a[0]), "r"(a[1]), "r"(a[2]), "r"(a[3]), "r"(b[0]), "r"(b[1]));
}

// ---------------------------------------------------------------------------
__global__ void k_deg_count(const int* __restrict__ dst, int E) {
    int i = blockIdx.x * blockDim.x + threadIdx.x;
    int stride = gridDim.x * blockDim.x;
    int E4 = E >> 2;
    const int4* dst4 = (const int4*)dst;
    for (int j = i; j < E4; j += stride) {
        int4 d = dst4[j];
        atomicAdd(&g_deg[d.x], 1);
        atomicAdd(&g_deg[d.y], 1);
        atomicAdd(&g_deg[d.z], 1);
        atomicAdd(&g_deg[d.w], 1);
    }
    for (int j = (E4 << 2) + i; j < E; j += stride)
        atomicAdd(&g_deg[dst[j]], 1);
}

// --- 3-phase exclusive scan of g_deg -> g_rowptr ---------------------------
__global__ void k_scan_part(int n) {
    __shared__ int s[256];
    int t = threadIdx.x;
    int i = blockIdx.x * 256 + t;
    int v = (i < n) ? g_deg[i] : 0;
    s[t] = v;
    __syncthreads();
    #pragma unroll
    for (int off = 1; off < 256; off <<= 1) {
        int u = (t >= off) ? s[t - off] : 0;
        __syncthreads();
        s[t] += u;
        __syncthreads();
    }
    if (i < n) g_rowptr[i] = s[t] - v;
    if (t == 255) g_part[blockIdx.x] = s[255];
}

__global__ void k_scan_mid(int nb) {
    __shared__ int s[512];
    int t = threadIdx.x;
    int v = (t < nb) ? g_part[t] : 0;
    s[t] = v;
    __syncthreads();
    #pragma unroll
    for (int off = 1; off < 512; off <<= 1) {
        int u = (t >= off) ? s[t - off] : 0;
        __syncthreads();
        s[t] += u;
        __syncthreads();
    }
    if (t < nb) g_part[t] = s[t] - v;
}

__global__ void k_scan_apply(int n) {
    int i = blockIdx.x * 256 + threadIdx.x;
    if (i < n) {
        g_rowptr[i] += g_part[blockIdx.x];
        g_dinv[i] = rsqrtf((float)(g_deg[i] + 1));
    }
}

// Bumps g_rowptr[d]; after this kernel g_rowptr[i] = row end.
__global__ void k_fill(const int* __restrict__ src,
                       const int* __restrict__ dst, int E) {
    int i = blockIdx.x * blockDim.x + threadIdx.x;
    int stride = gridDim.x * blockDim.x;
    int E4 = E >> 2;
    const int4* src4 = (const int4*)src;
    const int4* dst4 = (const int4*)dst;
    for (int j = i; j < E4; j += stride) {
        int4 s = src4[j];
        int4 d = dst4[j];
        int p0 = atomicAdd(&g_rowptr[d.x], 1);
        g_csr[p0] = make_int2(s.x, __float_as_int(g_dinv[s.x] * g_dinv[d.x]));
        int p1 = atomicAdd(&g_rowptr[d.y], 1);
        g_csr[p1] = make_int2(s.y, __float_as_int(g_dinv[s.y] * g_dinv[d.y]));
        int p2 = atomicAdd(&g_rowptr[d.z], 1);
        g_csr[p2] = make_int2(s.z, __float_as_int(g_dinv[s.z] * g_dinv[d.z]));
        int p3 = atomicAdd(&g_rowptr[d.w], 1);
        g_csr[p3] = make_int2(s.w, __float_as_int(g_dinv[s.w] * g_dinv[d.w]));
    }
    for (int j = (E4 << 2) + i; j < E; j += stride) {
        int s = src[j], d = dst[j];
        int p = atomicAdd(&g_rowptr[d], 1);
        g_csr[p] = make_int2(s, __float_as_int(g_dinv[s] * g_dinv[d]));
    }
}

// ---------------------------------------------------------------------------
// Tensor-core GEMM: 64x64 tile per block, 256 threads = 8 warps.
// Warp w: rows 16*(w&3), cols 32*(w>>2). fp16 inputs, fp32 accumulate.
// Emits fp16 table row + fp32 init = dinv^2*acc + bias.
template<int K, bool RELU, bool READ_GH, bool STORE_GH>
__global__ void k_gemm(const float* __restrict__ Xp,
                       const float* __restrict__ W,
                       const float* __restrict__ bias,
                       float* __restrict__ outp,
                       int n)
{
    constexpr int SA = K + 8;   // A row stride in halves (272B/144B: conflict-free ldmatrix)
    constexpr int SB = 72;      // B row stride in halves (144B)
    __shared__ __half As[64 * SA];
    __shared__ __half Bs[K * SB];

    const float* __restrict__ X = READ_GH ? (const float*)g_h : Xp;
    float* __restrict__ oinit = STORE_GH ? (float*)g_h : outp;
    __half* __restrict__ xwh = (__half*)g_xwh;

    int tid = threadIdx.x;
    int warp = tid >> 5;
    int lane = tid & 31;
    int row0 = blockIdx.x * 64;

    // W [K][64] fp32 -> Bs fp16
    for (int i = tid; i < K * 64; i += 256) {
        int k = i >> 6, nn = i & 63;
        Bs[k * SB + nn] = __float2half_rn(W[i]);
    }
    // X rows -> As fp16 (optional RELU), zero-pad OOB rows
    {
        const int KQ = K / 4;
        for (int i = tid; i < 64 * KQ; i += 256) {
            int r = i / KQ;
            int k4 = (i - r * KQ) * 4;
            int rr = row0 + r;
            float4 v = make_float4(0.f, 0.f, 0.f, 0.f);
            if (rr < n)
                v = ((const float4*)X)[((size_t)rr * K + k4) >> 2];
            if (RELU) {
                v.x = fmaxf(v.x, 0.f); v.y = fmaxf(v.y, 0.f);
                v.z = fmaxf(v.z, 0.f); v.w = fmaxf(v.w, 0.f);
            }
            __half2* dst2 = (__half2*)&As[r * SA + k4];
            dst2[0] = __floats2half2_rn(v.x, v.y);
            dst2[1] = __floats2half2_rn(v.z, v.w);
        }
    }
    __syncthreads();

    const int wr = (warp & 3) * 16;   // warp row base within tile
    const int wc = (warp >> 2) * 32;  // warp col base

    float d[4][4];
    #pragma unroll
    for (int f = 0; f < 4; ++f)
        #pragma unroll
        for (int i = 0; i < 4; ++i) d[f][i] = 0.f;

    // per-lane ldmatrix base addresses (k0 added in the loop)
    unsigned baseA = s2u(&As[(wr + (lane & 15)) * SA + (lane >> 4) * 8]);
    unsigned baseB0 = s2u(&Bs[(lane & 15) * SB + wc + (lane >> 4) * 8]);
    unsigned baseB1 = s2u(&Bs[(lane & 15) * SB + wc + 16 + (lane >> 4) * 8]);

    #pragma unroll
    for (int k0 = 0; k0 < K; k0 += 16) {
        unsigned a[4], b[8];
        ldmx4 (a,     baseA  + k0 * 2);
        ldmx4t(b,     baseB0 + k0 * SB * 2);
        ldmx4t(b + 4, baseB1 + k0 * SB * 2);
        mma16816(d[0], a, b + 0);   // cols wc..wc+7
        mma16816(d[1], a, b + 2);   // cols wc+8..15
        mma16816(d[2], a, b + 4);   // cols wc+16..23
        mma16816(d[3], a, b + 6);   // cols wc+24..31
    }

    // Epilogue: lane l owns (row = wr + l/4 [+8], cols c, c+1) per fragment.
    int rA = row0 + wr + (lane >> 2);
    int rB = rA + 8;
    float diA = (rA < n) ? g_dinv[rA] : 0.f;
    float diB = (rB < n) ? g_dinv[rB] : 0.f;
    float sA = diA * diA, sB = diB * diB;
    #pragma unroll
    for (int f = 0; f < 4; ++f) {
        int c = wc + f * 8 + 2 * (lane & 3);
        float b0 = bias[c], b1 = bias[c + 1];
        if (rA < n) {
            *(__half2*)&xwh[(size_t)rA * 64 + c] = __floats2half2_rn(d[f][0], d[f][1]);
            float2 o2 = make_float2(fmaf(sA, d[f][0], b0), fmaf(sA, d[f][1], b1));
            *(float2*)&oinit[(size_t)rA * 64 + c] = o2;
        }
        if (rB < n) {
            *(__half2*)&xwh[(size_t)rB * 64 + c] = __floats2half2_rn(d[f][2], d[f][3]);
            float2 o2 = make_float2(fmaf(sB, d[f][2], b0), fmaf(sB, d[f][3], b1));
            *(float2*)&oinit[(size_t)rB * 64 + c] = o2;
        }
    }
}

// ---------------------------------------------------------------------------
// Gather aggregation: 8-lane group per node, lane owns 8 features (uint4 =
// 8 halves, one 16B L2-only load per edge per lane). Accumulates fp32, adds
// the GEMM-written fp32 init rows, stores fp32.
template<bool TO_GH>
__global__ void k_aggr(float4* __restrict__ outp, int n)
{
    float4* __restrict__ o = TO_GH ? g_h : outp;
    const uint4* __restrict__ xwh = g_xwh;

    int gtid = blockIdx.x * blockDim.x + threadIdx.x;
    int node = gtid >> 3;
    int lane = threadIdx.x & 7;
    if (node >= n) return;

    int end = g_rowptr[node];
    int deg = g_deg[node];
    int beg = end - deg;

    float acc[8];
    #pragma unroll
    for (int i = 0; i < 8; ++i) acc[i] = 0.f;

    #define ACC_EDGE(q, sw) do {                                             \
        float w_ = __int_as_float((sw).y);                                   \
        float2 p0_ = h2f((q).x);                                             \
        float2 p1_ = h2f((q).y);                                             \
        float2 p2_ = h2f((q).z);                                             \
        float2 p3_ = h2f((q).w);                                             \
        acc[0] = fmaf(w_, p0_.x, acc[0]); acc[1] = fmaf(w_, p0_.y, acc[1]);  \
        acc[2] = fmaf(w_, p1_.x, acc[2]); acc[3] = fmaf(w_, p1_.y, acc[3]);  \
        acc[4] = fmaf(w_, p2_.x, acc[4]); acc[5] = fmaf(w_, p2_.y, acc[5]);  \
        acc[6] = fmaf(w_, p3_.x, acc[6]); acc[7] = fmaf(w_, p3_.y, acc[7]);  \
    } while (0)

    int e = beg;
    for (; e + 4 <= end; e += 4) {
        int2 sw0 = g_csr[e];
        int2 sw1 = g_csr[e + 1];
        int2 sw2 = g_csr[e + 2];
        int2 sw3 = g_csr[e + 3];
        uint4 q0 = __ldcg(xwh + (size_t)sw0.x * FU4 + lane);
        uint4 q1 = __ldcg(xwh + (size_t)sw1.x * FU4 + lane);
        uint4 q2 = __ldcg(xwh + (size_t)sw2.x * FU4 + lane);
        uint4 q3 = __ldcg(xwh + (size_t)sw3.x * FU4 + lane);
        ACC_EDGE(q0, sw0);
        ACC_EDGE(q1, sw1);
        ACC_EDGE(q2, sw2);
        ACC_EDGE(q3, sw3);
    }
    for (; e < end; ++e) {
        int2 sw = g_csr[e];
        uint4 q = __ldcg(xwh + (size_t)sw.x * FU4 + lane);
        ACC_EDGE(q, sw);
    }
    #undef ACC_EDGE

    float4* p = o + (size_t)node * F4 + 2 * lane;
    float4 i0 = p[0];
    float4 i1 = p[1];
    i0.x += acc[0]; i0.y += acc[1]; i0.z += acc[2]; i0.w += acc[3];
    i1.x += acc[4]; i1.y += acc[5]; i1.z += acc[6]; i1.w += acc[7];
    p[0] = i0;
    p[1] = i1;
}

// ---------------------------------------------------------------------------
extern "C" void kernel_launch(void* const* d_in, const int* in_sizes, int n_in,
                              void* d_out, int out_size)
{
    const float* x  = (const float*)d_in[0];
    const int*   ei = (const int*)d_in[1];
    const float* W1 = (const float*)d_in[2];
    const float* b1 = (const float*)d_in[3];
    const float* W2 = (const float*)d_in[4];
    const float* b2 = (const float*)d_in[5];
    float* out = (float*)d_out;

    const int IN = 128;
    int N = in_sizes[0] / IN;
    int E = in_sizes[1] / 2;
    const int* src = ei;
    const int* dst = ei + E;

    int nb256 = (N + 255) / 256;
    int gemm_blocks = (N + 63) / 64;
    int edge_blocks = 1184;
    int aggr_blocks = (N + 31) / 32;

    // --- graph preprocessing ---
    void* degptr = nullptr;
    cudaGetSymbolAddress(&degptr, g_deg);
    cudaMemsetAsync(degptr, 0, (size_t)N * sizeof(int));
    k_deg_count<<<edge_blocks, 256>>>(dst, E);
    k_scan_part<<<nb256, 256>>>(N);
    k_scan_mid<<<1, 512>>>(nb256);
    k_scan_apply<<<nb256, 256>>>(N);
    k_fill<<<edge_blocks, 256>>>(src, dst, E);

    // --- layer 1: init rows -> g_h, aggregate into g_h ---
    k_gemm<128, false, false, true><<<gemm_blocks, 256>>>(x, W1, b1, nullptr, N);
    k_aggr<true><<<aggr_blocks, 256>>>(nullptr, N);

    // --- layer 2: init rows -> out, aggregate into out ---
    k_gemm<64, true, true, false><<<gemm_blocks, 256>>>(nullptr, W2, b2, out, N);
    k_aggr<false><<<aggr_blocks, 256>>>((float4*)out, N);
}

// round 14
// speedup vs baseline: 1.8234x; 1.1335x over previous
#include <cuda_runtime.h>
#include <cuda_fp16.h>

// ---------------------------------------------------------------------------
// GCN_11682311045288: 2-layer GCN via per-launch CSR build + gather aggregation.
// fp16 message table pre-scaled by dinv[src] (CSR = 4B src index per edge);
// fp32 self-loop+bias path; tensor-core (HMMA) GEMM.
// Inputs: x [N,128] f32, edge_index [2,E] int32, W1[128,64], b1[64], W2[64,64], b2[64]
// Output: z [N,64] f32
// ---------------------------------------------------------------------------

#define MAXN 131072
#define MAXE 2097152
#define F 64
#define F4 (F / 4)    // float4 groups per fp32 row: 16
#define FU4 8         // uint4 (8 halves) groups per fp16 row: 64/8 = 8

// Scratch (module-load allocated; allowed).
__device__ uint4  g_xwh[(size_t)MAXN * FU4];  // fp16 dinv[src]*XW table, 128B/row
__device__ float4 g_h [(size_t)MAXN * F4];    // layer-1 result / layer-2 input
__device__ float  g_dinv[MAXN];
__device__ int    g_deg [MAXN];
__device__ int    g_rowptr[MAXN];             // after k_fill: row end
__device__ int    g_part[512];
__device__ int    g_csr[MAXE];                // src index per edge

__device__ __forceinline__ float2 h2f(unsigned u) {
    __half2 h = *reinterpret_cast<__half2*>(&u);
    return __half22float2(h);
}
__device__ __forceinline__ unsigned s2u(const void* p) {
    return (unsigned)__cvta_generic_to_shared(p);
}
__device__ __forceinline__ void ldmx4(unsigned* r, unsigned addr) {
    asm volatile("ldmatrix.sync.aligned.m8n8.x4.shared.b16 {%0,%1,%2,%3}, [%4];"
                 : "=r"(r[0]), "=r"(r[1]), "=r"(r[2]), "=r"(r[3]) : "r"(addr));
}
__device__ __forceinline__ void ldmx4t(unsigned* r, unsigned addr) {
    asm volatile("ldmatrix.sync.aligned.m8n8.x4.trans.shared.b16 {%0,%1,%2,%3}, [%4];"
                 : "=r"(r[0]), "=r"(r[1]), "=r"(r[2]), "=r"(r[3]) : "r"(addr));
}
__device__ __forceinline__ void mma16816(float* d, const unsigned* a, const unsigned* b) {
    asm volatile(
        "mma.sync.aligned.m16n8k16.row.col.f32.f16.f16.f32 "
        "{%0,%1,%2,%3}, {%4,%5,%6,%7}, {%8,%9}, {%0,%1,%2,%3};"
        : "+f"(d[0]), "+f"(d[1]), "+f"(d[2]), "+f"(d[3])
        : "r"(a[0]), "r"(a[1]), "r"(a[2]), "r"(a[3]), "r"(b[0]), "r"(b[1]));
}

// ---------------------------------------------------------------------------
__global__ void k_deg_count(const int* __restrict__ dst, int E) {
    int i = blockIdx.x * blockDim.x + threadIdx.x;
    int stride = gridDim.x * blockDim.x;
    int E4 = E >> 2;
    const int4* dst4 = (const int4*)dst;
    for (int j = i; j < E4; j += stride) {
        int4 d = dst4[j];
        atomicAdd(&g_deg[d.x], 1);
        atomicAdd(&g_deg[d.y], 1);
        atomicAdd(&g_deg[d.z], 1);
        atomicAdd(&g_deg[d.w], 1);
    }
    for (int j = (E4 << 2) + i; j < E; j += stride)
        atomicAdd(&g_deg[dst[j]], 1);
}

// --- 3-phase exclusive scan of g_deg -> g_rowptr ---------------------------
__global__ void k_scan_part(int n) {
    __shared__ int s[256];
    int t = threadIdx.x;
    int i = blockIdx.x * 256 + t;
    int v = (i < n) ? g_deg[i] : 0;
    s[t] = v;
    __syncthreads();
    #pragma unroll
    for (int off = 1; off < 256; off <<= 1) {
        int u = (t >= off) ? s[t - off] : 0;
        __syncthreads();
        s[t] += u;
        __syncthreads();
    }
    if (i < n) g_rowptr[i] = s[t] - v;
    if (t == 255) g_part[blockIdx.x] = s[255];
}

__global__ void k_scan_mid(int nb) {
    __shared__ int s[512];
    int t = threadIdx.x;
    int v = (t < nb) ? g_part[t] : 0;
    s[t] = v;
    __syncthreads();
    #pragma unroll
    for (int off = 1; off < 512; off <<= 1) {
        int u = (t >= off) ? s[t - off] : 0;
        __syncthreads();
        s[t] += u;
        __syncthreads();
    }
    if (t < nb) g_part[t] = s[t] - v;
}

__global__ void k_scan_apply(int n) {
    int i = blockIdx.x * 256 + threadIdx.x;
    if (i < n) {
        g_rowptr[i] += g_part[blockIdx.x];
        g_dinv[i] = rsqrtf((float)(g_deg[i] + 1));
    }
}

// Counting sort of src by dst. Bumps g_rowptr[d]; afterwards rowptr = row end.
__global__ void k_fill(const int* __restrict__ src,
                       const int* __restrict__ dst, int E) {
    int i = blockIdx.x * blockDim.x + threadIdx.x;
    int stride = gridDim.x * blockDim.x;
    int E4 = E >> 2;
    const int4* src4 = (const int4*)src;
    const int4* dst4 = (const int4*)dst;
    for (int j = i; j < E4; j += stride) {
        int4 s = src4[j];
        int4 d = dst4[j];
        g_csr[atomicAdd(&g_rowptr[d.x], 1)] = s.x;
        g_csr[atomicAdd(&g_rowptr[d.y], 1)] = s.y;
        g_csr[atomicAdd(&g_rowptr[d.z], 1)] = s.z;
        g_csr[atomicAdd(&g_rowptr[d.w], 1)] = s.w;
    }
    for (int j = (E4 << 2) + i; j < E; j += stride)
        g_csr[atomicAdd(&g_rowptr[dst[j]], 1)] = src[j];
}

// ---------------------------------------------------------------------------
// Tensor-core GEMM: 64x64 tile per block, 256 threads = 8 warps.
// Warp w: rows 16*(w&3), cols 32*(w>>2). fp16 inputs, fp32 accumulate.
// Emits: fp16 table row = dinv[r]*acc, fp32 init = dinv[r]^2*acc + bias.
template<int K, bool RELU, bool READ_GH, bool STORE_GH>
__global__ void k_gemm(const float* __restrict__ Xp,
                       const float* __restrict__ W,
                       const float* __restrict__ bias,
                       float* __restrict__ outp,
                       int n)
{
    constexpr int SA = K + 8;   // A row stride in halves
    constexpr int SB = 72;      // B row stride in halves
    __shared__ __half As[64 * SA];
    __shared__ __half Bs[K * SB];

    const float* __restrict__ X = READ_GH ? (const float*)g_h : Xp;
    float* __restrict__ oinit = STORE_GH ? (float*)g_h : outp;
    __half* __restrict__ xwh = (__half*)g_xwh;

    int tid = threadIdx.x;
    int warp = tid >> 5;
    int lane = tid & 31;
    int row0 = blockIdx.x * 64;

    for (int i = tid; i < K * 64; i += 256) {
        int k = i >> 6, nn = i & 63;
        Bs[k * SB + nn] = __float2half_rn(W[i]);
    }
    {
        const int KQ = K / 4;
        for (int i = tid; i < 64 * KQ; i += 256) {
            int r = i / KQ;
            int k4 = (i - r * KQ) * 4;
            int rr = row0 + r;
            float4 v = make_float4(0.f, 0.f, 0.f, 0.f);
            if (rr < n)
                v = ((const float4*)X)[((size_t)rr * K + k4) >> 2];
            if (RELU) {
                v.x = fmaxf(v.x, 0.f); v.y = fmaxf(v.y, 0.f);
                v.z = fmaxf(v.z, 0.f); v.w = fmaxf(v.w, 0.f);
            }
            __half2* dst2 = (__half2*)&As[r * SA + k4];
            dst2[0] = __floats2half2_rn(v.x, v.y);
            dst2[1] = __floats2half2_rn(v.z, v.w);
        }
    }
    __syncthreads();

    const int wr = (warp & 3) * 16;
    const int wc = (warp >> 2) * 32;

    float d[4][4];
    #pragma unroll
    for (int f = 0; f < 4; ++f)
        #pragma unroll
        for (int i = 0; i < 4; ++i) d[f][i] = 0.f;

    unsigned baseA = s2u(&As[(wr + (lane & 15)) * SA + (lane >> 4) * 8]);
    unsigned baseB0 = s2u(&Bs[(lane & 15) * SB + wc + (lane >> 4) * 8]);
    unsigned baseB1 = s2u(&Bs[(lane & 15) * SB + wc + 16 + (lane >> 4) * 8]);

    #pragma unroll
    for (int k0 = 0; k0 < K; k0 += 16) {
        unsigned a[4], b[8];
        ldmx4 (a,     baseA  + k0 * 2);
        ldmx4t(b,     baseB0 + k0 * SB * 2);
        ldmx4t(b + 4, baseB1 + k0 * SB * 2);
        mma16816(d[0], a, b + 0);
        mma16816(d[1], a, b + 2);
        mma16816(d[2], a, b + 4);
        mma16816(d[3], a, b + 6);
    }

    int rA = row0 + wr + (lane >> 2);
    int rB = rA + 8;
    float diA = (rA < n) ? g_dinv[rA] : 0.f;
    float diB = (rB < n) ? g_dinv[rB] : 0.f;
    float sA = diA * diA, sB = diB * diB;
    #pragma unroll
    for (int f = 0; f < 4; ++f) {
        int c = wc + f * 8 + 2 * (lane & 3);
        float b0 = bias[c], b1 = bias[c + 1];
        if (rA < n) {
            *(__half2*)&xwh[(size_t)rA * 64 + c] =
                __floats2half2_rn(diA * d[f][0], diA * d[f][1]);
            float2 o2 = make_float2(fmaf(sA, d[f][0], b0), fmaf(sA, d[f][1], b1));
            *(float2*)&oinit[(size_t)rA * 64 + c] = o2;
        }
        if (rB < n) {
            *(__half2*)&xwh[(size_t)rB * 64 + c] =
                __floats2half2_rn(diB * d[f][2], diB * d[f][3]);
            float2 o2 = make_float2(fmaf(sB, d[f][2], b0), fmaf(sB, d[f][3], b1));
            *(float2*)&oinit[(size_t)rB * 64 + c] = o2;
        }
    }
}

// ---------------------------------------------------------------------------
// Gather aggregation: 8-lane group per node, lane owns 8 features.
// Messages are pre-scaled by dinv[src] -> inner loop is pure adds;
// multiply by dinv[node] once at the end, then add the fp32 init row.
template<bool TO_GH>
__global__ void k_aggr(float4* __restrict__ outp, int n)
{
    float4* __restrict__ o = TO_GH ? g_h : outp;
    const uint4* __restrict__ xwh = g_xwh;

    int gtid = blockIdx.x * blockDim.x + threadIdx.x;
    int node = gtid >> 3;
    int lane = threadIdx.x & 7;
    if (node >= n) return;

    int end = g_rowptr[node];
    int deg = g_deg[node];
    int beg = end - deg;

    float acc[8];
    #pragma unroll
    for (int i = 0; i < 8; ++i) acc[i] = 0.f;

    #define ACC_EDGE(q) do {                                                 \
        float2 p0_ = h2f((q).x);                                             \
        float2 p1_ = h2f((q).y);                                             \
        float2 p2_ = h2f((q).z);                                             \
        float2 p3_ = h2f((q).w);                                             \
        acc[0] += p0_.x; acc[1] += p0_.y;                                    \
        acc[2] += p1_.x; acc[3] += p1_.y;                                    \
        acc[4] += p2_.x; acc[5] += p2_.y;                                    \
        acc[6] += p3_.x; acc[7] += p3_.y;                                    \
    } while (0)

    int e = beg;
    for (; e + 4 <= end; e += 4) {
        int s0 = g_csr[e];
        int s1 = g_csr[e + 1];
        int s2 = g_csr[e + 2];
        int s3 = g_csr[e + 3];
        uint4 q0 = __ldcg(xwh + (size_t)s0 * FU4 + lane);
        uint4 q1 = __ldcg(xwh + (size_t)s1 * FU4 + lane);
        uint4 q2 = __ldcg(xwh + (size_t)s2 * FU4 + lane);
        uint4 q3 = __ldcg(xwh + (size_t)s3 * FU4 + lane);
        ACC_EDGE(q0);
        ACC_EDGE(q1);
        ACC_EDGE(q2);
        ACC_EDGE(q3);
    }
    for (; e < end; ++e) {
        uint4 q = __ldcg(xwh + (size_t)g_csr[e] * FU4 + lane);
        ACC_EDGE(q);
    }
    #undef ACC_EDGE

    float dn = g_dinv[node];
    float4* p = o + (size_t)node * F4 + 2 * lane;
    float4 i0 = p[0];
    float4 i1 = p[1];
    i0.x = fmaf(dn, acc[0], i0.x); i0.y = fmaf(dn, acc[1], i0.y);
    i0.z = fmaf(dn, acc[2], i0.z); i0.w = fmaf(dn, acc[3], i0.w);
    i1.x = fmaf(dn, acc[4], i1.x); i1.y = fmaf(dn, acc[5], i1.y);
    i1.z = fmaf(dn, acc[6], i1.z); i1.w = fmaf(dn, acc[7], i1.w);
    p[0] = i0;
    p[1] = i1;
}

// ---------------------------------------------------------------------------
extern "C" void kernel_launch(void* const* d_in, const int* in_sizes, int n_in,
                              void* d_out, int out_size)
{
    const float* x  = (const float*)d_in[0];
    const int*   ei = (const int*)d_in[1];
    const float* W1 = (const float*)d_in[2];
    const float* b1 = (const float*)d_in[3];
    const float* W2 = (const float*)d_in[4];
    const float* b2 = (const float*)d_in[5];
    float* out = (float*)d_out;

    const int IN = 128;
    int N = in_sizes[0] / IN;
    int E = in_sizes[1] / 2;
    const int* src = ei;
    const int* dst = ei + E;

    int nb256 = (N + 255) / 256;
    int gemm_blocks = (N + 63) / 64;
    int edge_blocks = 1184;
    int aggr_blocks = (N + 31) / 32;

    // --- graph preprocessing ---
    void* degptr = nullptr;
    cudaGetSymbolAddress(&degptr, g_deg);
    cudaMemsetAsync(degptr, 0, (size_t)N * sizeof(int));
    k_deg_count<<<edge_blocks, 256>>>(dst, E);
    k_scan_part<<<nb256, 256>>>(N);
    k_scan_mid<<<1, 512>>>(nb256);
    k_scan_apply<<<nb256, 256>>>(N);
    k_fill<<<edge_blocks, 256>>>(src, dst, E);

    // --- layer 1: init rows -> g_h, aggregate into g_h ---
    k_gemm<128, false, false, true><<<gemm_blocks, 256>>>(x, W1, b1, nullptr, N);
    k_aggr<true><<<aggr_blocks, 256>>>(nullptr, N);

    // --- layer 2: init rows -> out, aggregate into out ---
    k_gemm<64, true, true, false><<<gemm_blocks, 256>>>(nullptr, W2, b2, out, N);
    k_aggr<false><<<aggr_blocks, 256>>>((float4*)out, N);
}